// round 16
// baseline (speedup 1.0000x reference)
#include <cuda_runtime.h>
#include <cuda_fp16.h>

typedef unsigned int u32;

#define T_FRAMES 5
#define HEADS 6
#define DIM 192
#define HDIM 32
#define NTOK 320

// ---------------- small helpers ----------------
__device__ __forceinline__ float lds32fv(u32 a) {   // volatile: bias rewritten per head
    float r; asm volatile("ld.shared.b32 %0,[%1];" : "=f"(r) : "r"(a)); return r;
}
__device__ __forceinline__ void ldsm4(u32 &r0, u32 &r1, u32 &r2, u32 &r3, u32 a) {
    asm("ldmatrix.sync.aligned.m8n8.x4.shared.b16 {%0,%1,%2,%3},[%4];"
        : "=r"(r0), "=r"(r1), "=r"(r2), "=r"(r3) : "r"(a));
}
__device__ __forceinline__ void ldsm4v(u32 &r0, u32 &r1, u32 &r2, u32 &r3, u32 a) {
    asm volatile("ldmatrix.sync.aligned.m8n8.x4.shared.b16 {%0,%1,%2,%3},[%4];"
        : "=r"(r0), "=r"(r1), "=r"(r2), "=r"(r3) : "r"(a));
}
__device__ __forceinline__ void ldsm4tv(u32 &r0, u32 &r1, u32 &r2, u32 &r3, u32 a) {
    asm volatile("ldmatrix.sync.aligned.m8n8.x4.trans.shared.b16 {%0,%1,%2,%3},[%4];"
        : "=r"(r0), "=r"(r1), "=r"(r2), "=r"(r3) : "r"(a));
}
// fp16 mma m16n8k16, fp32 accumulate
__device__ __forceinline__ void mma16816(float &c0, float &c1, float &c2, float &c3,
                                         u32 a0, u32 a1, u32 a2, u32 a3,
                                         u32 b0, u32 b1) {
    asm("mma.sync.aligned.m16n8k16.row.col.f32.f16.f16.f32 "
        "{%0,%1,%2,%3},{%4,%5,%6,%7},{%8,%9},{%0,%1,%2,%3};"
        : "+f"(c0), "+f"(c1), "+f"(c2), "+f"(c3)
        : "r"(a0), "r"(a1), "r"(a2), "r"(a3), "r"(b0), "r"(b1));
}
__device__ __forceinline__ u32 packh2(float a, float b) {
    __half2 hv = __floats2half2_rn(a, b);
    return *(u32*)&hv;
}
__device__ __forceinline__ u32 h2exp2(u32 s) {
    u32 r; asm("ex2.approx.f16x2 %0,%1;" : "=r"(r) : "r"(s)); return r;
}
__device__ __forceinline__ u32 hadd2(u32 a, u32 b) {
    u32 r; asm("add.rn.f16x2 %0,%1,%2;" : "=r"(r) : "r"(a), "r"(b)); return r;
}

// ---------------- fused kernel: one CTA per window ----------------
// Phase 1 (x6 heads): stage Q/K/V(head) -> attention -> O columns into smem.
// Phase 2: overlay W onto the QKV region -> proj + bias + window-reverse.
// Warp owns tokens [16w, 16w+16) in BOTH phases -> O needs no cross-warp sync.
#define ROWB 80          // Q/K/V row bytes (40 fp16)
#define OROW 400         // O / W row bytes (200 fp16); 400 % 128 = 16 -> conflict-free
#define OFF_Q    0
#define OFF_K    25600
#define OFF_V    51200
#define OFF_W    0       // phase-2 overlay of Q/K/V
#define OFF_O    76800   // 320 x 400 = 128000
#define OFF_BIAS 204800  // 1185 floats
#define OFF_META 209540  // 320 ints
#define SMEM_TOTAL 210944

__global__ void __launch_bounds__(640)
fused_kernel(const float* __restrict__ qkv, const float* __restrict__ bias_table,
             const float* __restrict__ pw, const float* __restrict__ pb,
             float* __restrict__ out)
{
    extern __shared__ char smc[];
    const u32 smb = (u32)__cvta_generic_to_shared(smc);
    int* meta_s = (int*)(smc + OFF_META);

    const int wb   = blockIdx.x;          // b*64 + widx
    const int b    = wb >> 6;
    const int widx = wb & 63;
    const int hw = widx >> 3, ww = widx & 7;

    const int tid  = threadIdx.x;         // 0..639
    const int lane = tid & 31;
    const int warp = tid >> 5;            // 0..19
    const int g    = lane >> 2;
    const int t4   = lane & 3;
    const int wr   = warp * 16;           // this warp's 16 token rows (both phases)

    // staging roles: threads 0..319 stage Q+K of token tid; 320..639 stage V
    const bool qk_half = tid < 320;
    const int tok = qk_half ? tid : tid - 320;
    const int t   = tok >> 6;
    const int hs  = (tok >> 3) & 7;
    const int wsv = tok & 7;
    const int Hp = hw * 8 + hs;
    const int Wp = ww * 8 + wsv;
    const int h = (Hp + 4) & 63;
    const int w = (Wp + 4) & 63;
    const int rh = (Hp < 56) ? 0 : ((Hp < 60) ? 1 : 2);
    const int rw = (Wp < 56) ? 0 : ((Wp < 60) ? 1 : 2);
    if (qk_half)
        meta_s[tok] = (t * 15 + hs + wsv) | ((rh * 3 + rw) << 8);

    const int row = ((b * T_FRAMES + t) << 12) + (h << 6) + w;
    const size_t rowoff = (size_t)row * (3 * DIM);

    const float LOG2E = 1.4426950408889634f;
    const float qs_f = 0.17677669529663687f * LOG2E;

    __syncthreads();   // meta visible

    int ai[2], ri[2];
    #pragma unroll
    for (int hh = 0; hh < 2; ++hh) {
        int mv = meta_s[wr + g + 8 * hh];
        ai[hh] = (mv & 255) + 112;
        ri[hh] = mv >> 8;
    }

    // ldmatrix per-lane address components
    const int l8  = lane & 7;
    const u32 krb = (u32)(l8 * ROWB + (lane >> 3) * 16);
    const u32 qrb = (u32)((wr + l8 + ((lane >> 3) & 1) * 8) * ROWB + (lane >> 4) * 16);
    const u32 vtb = smb + OFF_V + (u32)(lane * ROWB);      // V trans: lane = key row
    const u32 khb = smb + OFF_K + krb;
    const u32 bib = smb + OFF_BIAS;

    // ================= Phase 1: attention, 6 heads =================
    #pragma unroll 1
    for (int hd = 0; hd < HEADS; ++hd) {
        if (hd) __syncthreads();          // previous head's fragment reads done
        const float* qp = qkv + rowoff + hd * HDIM;
        if (qk_half) {
            const float4* qv = (const float4*)qp;
            const float4* kv = (const float4*)(qp + DIM);
            #pragma unroll
            for (int m = 0; m < 8; ++m) {
                float4 f = qv[m];
                const int off = tok * ROWB + m * 8;
                *(u32*)(smc + OFF_Q + off)     = packh2(f.x * qs_f, f.y * qs_f);
                *(u32*)(smc + OFF_Q + off + 4) = packh2(f.z * qs_f, f.w * qs_f);
            }
            #pragma unroll
            for (int m = 0; m < 8; ++m) {
                float4 f = kv[m];
                const int off = tok * ROWB + m * 8;
                *(u32*)(smc + OFF_K + off)     = packh2(f.x, f.y);
                *(u32*)(smc + OFF_K + off + 4) = packh2(f.z, f.w);
            }
        } else {
            const float4* vv = (const float4*)(qp + 2 * DIM);
            #pragma unroll
            for (int m = 0; m < 8; ++m) {
                float4 f = vv[m];
                const int off = tok * ROWB + m * 8;
                *(u32*)(smc + OFF_V + off)     = packh2(f.x, f.y);
                *(u32*)(smc + OFF_V + off + 4) = packh2(f.z, f.w);
            }
        }
        for (int idx = tid; idx < 1185; idx += 640)
            *(float*)(smc + OFF_BIAS + idx * 4) = bias_table[idx * HEADS + hd] * LOG2E;
        __syncthreads();                  // staging visible

        // Q A-fragments for this head
        u32 qa[2][4];
        #pragma unroll
        for (int kt = 0; kt < 2; ++kt)
            ldsm4v(qa[kt][0], qa[kt][1], qa[kt][2], qa[kt][3],
                   smb + OFF_Q + qrb + kt * 32);

        float oacc[4][4];
        #pragma unroll
        for (int n = 0; n < 4; ++n)
            #pragma unroll
            for (int e = 0; e < 4; ++e) oacc[n][e] = 0.f;
        float lsum[2] = {0.f, 0.f};

        float sacc[4][4];
        u32 ps[4][2];

        auto s_block = [&](int jb2) {
            #pragma unroll
            for (int n = 0; n < 4; ++n) {
                const int j0 = jb2 + 8 * n + 2 * t4;
                const int mj0 = meta_s[j0], mj1 = meta_s[j0 + 1];
                const int b0i = mj0 & 255, b1i = mj1 & 255;
                const int rj0 = mj0 >> 8,  rj1 = mj1 >> 8;
                float* c = sacc[n];
                c[0] = (ri[0] == rj0) ? lds32fv(bib + (ai[0] - b0i) * 4) : -1e4f;
                c[1] = (ri[0] == rj1) ? lds32fv(bib + (ai[0] - b1i) * 4) : -1e4f;
                c[2] = (ri[1] == rj0) ? lds32fv(bib + (ai[1] - b0i) * 4) : -1e4f;
                c[3] = (ri[1] == rj1) ? lds32fv(bib + (ai[1] - b1i) * 4) : -1e4f;
            }
            #pragma unroll
            for (int n = 0; n < 4; ++n) {
                u32 kh[4];
                ldsm4v(kh[0], kh[1], kh[2], kh[3], khb + (jb2 + 8 * n) * ROWB);
                float* c = sacc[n];
                mma16816(c[0], c[1], c[2], c[3],
                         qa[0][0], qa[0][1], qa[0][2], qa[0][3], kh[0], kh[1]);
                mma16816(c[0], c[1], c[2], c[3],
                         qa[1][0], qa[1][1], qa[1][2], qa[1][3], kh[2], kh[3]);
            }
        };
        auto sm_n = [&](int n, u32& sum0, u32& sum1) {
            float* c = sacc[n];
            const u32 pk0 = h2exp2(packh2(c[0], c[1]));
            const u32 pk1 = h2exp2(packh2(c[2], c[3]));
            ps[n][0] = pk0;
            ps[n][1] = pk1;
            sum0 = hadd2(sum0, pk0);
            sum1 = hadd2(sum1, pk1);
        };
        auto pv_all = [&](int jb2) {
            const u32 vb = vtb + (u32)(jb2 * ROWB);
            #pragma unroll
            for (int n = 0; n < 4; ++n) {
                u32 vt[4];
                ldsm4tv(vt[0], vt[1], vt[2], vt[3], vb + n * 16);
                float* c = oacc[n];
                mma16816(c[0], c[1], c[2], c[3],
                         ps[0][0], ps[0][1], ps[1][0], ps[1][1], vt[0], vt[1]);
                mma16816(c[0], c[1], c[2], c[3],
                         ps[2][0], ps[2][1], ps[3][0], ps[3][1], vt[2], vt[3]);
            }
        };
        auto flush_sums = [&](u32 sum0, u32 sum1) {
            float2 f0 = __half22float2(*(__half2*)&sum0);
            float2 f1 = __half22float2(*(__half2*)&sum1);
            lsum[0] += f0.x + f0.y;
            lsum[1] += f1.x + f1.y;
        };

        s_block(0);
        #pragma unroll 1
        for (int jc = 0; jc < 9; ++jc) {
            const int jb = jc * 32;
            u32 sum0 = 0, sum1 = 0;
            sm_n(0, sum0, sum1);
            sm_n(1, sum0, sum1);
            sm_n(2, sum0, sum1);
            sm_n(3, sum0, sum1);
            s_block(jb + 32);
            pv_all(jb);
            flush_sums(sum0, sum1);
        }
        {
            u32 sum0 = 0, sum1 = 0;
            sm_n(0, sum0, sum1);
            sm_n(1, sum0, sum1);
            sm_n(2, sum0, sum1);
            sm_n(3, sum0, sum1);
            pv_all(288);
            flush_sums(sum0, sum1);
        }

        #pragma unroll
        for (int hh = 0; hh < 2; ++hh) {
            float v = lsum[hh];
            v += __shfl_xor_sync(0xffffffffu, v, 1);
            v += __shfl_xor_sync(0xffffffffu, v, 2);
            lsum[hh] = 1.0f / v;
        }

        // O (fp16, inv-scaled) into smem — same warp reads these rows in phase 2
        #pragma unroll
        for (int hh = 0; hh < 2; ++hh) {
            const int r = wr + g + 8 * hh;
            const float inv = lsum[hh];
            #pragma unroll
            for (int n = 0; n < 4; ++n)
                *(u32*)(smc + OFF_O + r * OROW + hd * 64 + 16 * n + 4 * t4) =
                    packh2(oacc[n][2 * hh] * inv, oacc[n][2 * hh + 1] * inv);
        }
    }

    // ================= Phase 2: projection + window-reverse =================
    __syncthreads();   // all K/V fragment reads done -> safe to overlay W
    for (int idx = tid; idx < DIM * 96; idx += 640) {
        const int c = idx / 96, kp = idx % 96;
        float2 v = *(const float2*)(pw + c * DIM + kp * 2);
        *(u32*)(smc + OFF_W + c * OROW + kp * 4) = packh2(v.x, v.y);
    }
    __syncthreads();   // W visible

    const u32 arb = (u32)((wr + l8 + ((lane >> 3) & 1) * 8) * OROW + (lane >> 4) * 16);
    const u32 brb = (u32)((l8 + (lane >> 4) * 8) * OROW + ((lane >> 3) & 1) * 16);
    const u32 ohb = smb + OFF_O + arb;
    const u32 whb = smb + OFF_W + brb;

    #pragma unroll 1
    for (int nh = 0; nh < 2; ++nh) {
        const int n0 = nh * 96;
        float pbv[12][2];
        #pragma unroll
        for (int nt = 0; nt < 12; ++nt) {
            float2 v = *(const float2*)(pb + n0 + nt * 8 + 2 * t4);
            pbv[nt][0] = v.x; pbv[nt][1] = v.y;
        }

        float acc[12][4];
        #pragma unroll
        for (int nt = 0; nt < 12; ++nt)
            #pragma unroll
            for (int e = 0; e < 4; ++e) acc[nt][e] = 0.f;

        #pragma unroll
        for (int ki = 0; ki < 12; ++ki) {
            u32 ah[4];
            ldsm4v(ah[0], ah[1], ah[2], ah[3], ohb + ki * 32);
            #pragma unroll
            for (int p = 0; p < 6; ++p) {
                u32 bh[4];
                ldsm4(bh[0], bh[1], bh[2], bh[3],
                      whb + (u32)((n0 + 16 * p) * OROW) + ki * 32);
                float* c0 = acc[2 * p];
                float* c1 = acc[2 * p + 1];
                mma16816(c0[0], c0[1], c0[2], c0[3], ah[0], ah[1], ah[2], ah[3], bh[0], bh[1]);
                mma16816(c1[0], c1[1], c1[2], c1[3], ah[0], ah[1], ah[2], ah[3], bh[2], bh[3]);
            }
        }

        // bias + window-reverse scatter
        #pragma unroll
        for (int hh = 0; hh < 2; ++hh) {
            const int s = wr + g + 8 * hh;   // token 0..319
            const int st = s >> 6;
            const int shs = (s >> 3) & 7, swv = s & 7;
            const int oh = (hw * 8 + shs + 4) & 63;
            const int ow = (ww * 8 + swv + 4) & 63;
            float* orow = out + ((size_t)((b * T_FRAMES + st) * 4096 + oh * 64 + ow)) * DIM + n0;
            #pragma unroll
            for (int nt = 0; nt < 12; ++nt) {
                float2 v = make_float2(acc[nt][2 * hh]     + pbv[nt][0],
                                       acc[nt][2 * hh + 1] + pbv[nt][1]);
                *(float2*)(orow + nt * 8 + 2 * t4) = v;
            }
        }
    }
}

// ---------------- launch ----------------
extern "C" void kernel_launch(void* const* d_in, const int* in_sizes, int n_in,
                              void* d_out, int out_size)
{
    const float* qkv        = (const float*)d_in[0];
    const float* bias_table = (const float*)d_in[1];
    const float* pw         = (const float*)d_in[2];
    const float* pb         = (const float*)d_in[3];
    float* out = (float*)d_out;

    int B = in_sizes[0] / (T_FRAMES * 64 * 64 * 3 * DIM);
    if (B < 1) B = 1;
    if (B > 2) B = 2;

    cudaFuncSetAttribute(fused_kernel, cudaFuncAttributeMaxDynamicSharedMemorySize, SMEM_TOTAL);
    fused_kernel<<<B * 64, 640, SMEM_TOTAL>>>(qkv, bias_table, pw, pb, out);
}

// round 17
// speedup vs baseline: 1.4826x; 1.4826x over previous
#include <cuda_runtime.h>
#include <cuda_fp16.h>

typedef unsigned int u32;

#define T_FRAMES 5
#define HEADS 6
#define DIM 192
#define HDIM 32
#define NTOK 320

// scratch: per-window attention output, fp16 (half2 packed in u32), [wb][n][DIM]
__device__ u32 g_scratch[2 * 64 * NTOK * DIM / 2];

// ---------------- small helpers ----------------
__device__ __forceinline__ float2 lds64fv(u32 a) {
    float2 r; asm volatile("ld.shared.v2.f32 {%0,%1},[%2];"
                           : "=f"(r.x), "=f"(r.y) : "r"(a));
    return r;
}
__device__ __forceinline__ void ldsm4(u32 &r0, u32 &r1, u32 &r2, u32 &r3, u32 a) {
    asm("ldmatrix.sync.aligned.m8n8.x4.shared.b16 {%0,%1,%2,%3},[%4];"
        : "=r"(r0), "=r"(r1), "=r"(r2), "=r"(r3) : "r"(a));
}
__device__ __forceinline__ void ldsm4t(u32 &r0, u32 &r1, u32 &r2, u32 &r3, u32 a) {
    asm("ldmatrix.sync.aligned.m8n8.x4.trans.shared.b16 {%0,%1,%2,%3},[%4];"
        : "=r"(r0), "=r"(r1), "=r"(r2), "=r"(r3) : "r"(a));
}
__device__ __forceinline__ void ldsm4v(u32 &r0, u32 &r1, u32 &r2, u32 &r3, u32 a) {
    asm volatile("ldmatrix.sync.aligned.m8n8.x4.shared.b16 {%0,%1,%2,%3},[%4];"
        : "=r"(r0), "=r"(r1), "=r"(r2), "=r"(r3) : "r"(a));
}
// fp16 mma m16n8k16, fp32 accumulate
__device__ __forceinline__ void mma16816(float &c0, float &c1, float &c2, float &c3,
                                         u32 a0, u32 a1, u32 a2, u32 a3,
                                         u32 b0, u32 b1) {
    asm("mma.sync.aligned.m16n8k16.row.col.f32.f16.f16.f32 "
        "{%0,%1,%2,%3},{%4,%5,%6,%7},{%8,%9},{%0,%1,%2,%3};"
        : "+f"(c0), "+f"(c1), "+f"(c2), "+f"(c3)
        : "r"(a0), "r"(a1), "r"(a2), "r"(a3), "r"(b0), "r"(b1));
}
__device__ __forceinline__ u32 packh2(float a, float b) {
    __half2 hv = __floats2half2_rn(a, b);
    return *(u32*)&hv;
}
__device__ __forceinline__ u32 h2exp2(u32 s) {
    u32 r; asm("ex2.approx.f16x2 %0,%1;" : "=r"(r) : "r"(s)); return r;
}
__device__ __forceinline__ u32 hadd2(u32 a, u32 b) {
    u32 r; asm("add.rn.f16x2 %0,%1,%2;" : "=r"(r) : "r"(a), "r"(b)); return r;
}

// ---------------- attention kernel (fp16 hi-only, paired-bias table) ----------------
// 640 threads / 20 warps; warp owns 16 query rows.
// Key pairs (j0 even, j0+1): same region, adjacent bias indices ->
// one meta load + one LDS.64 from the overlapped biasd table per (n,hh).
#define ROWB 80
#define OFF_QH    0
#define OFF_KH    25600
#define OFF_VH    51200
#define OFF_BIASD 76800      // 1186 float2 = 9488 B
#define OFF_META  86288      // 320 ints
#define ATTN_SMEM (87568)

__global__ void __launch_bounds__(640)
attn_kernel(const float* __restrict__ qkv, const float* __restrict__ bias_table)
{
    extern __shared__ char smc[];
    const u32 smb = (u32)__cvta_generic_to_shared(smc);
    int* meta_s = (int*)(smc + OFF_META);

    const int head = blockIdx.y;
    const int wb   = blockIdx.x;          // b*64 + widx
    const int b    = wb >> 6;
    const int widx = wb & 63;
    const int hw = widx >> 3, ww = widx & 7;

    const int tid  = threadIdx.x;         // 0..639
    const int lane = tid & 31;
    const int warp = tid >> 5;            // 0..19
    const int g    = lane >> 2;
    const int t4   = lane & 3;
    const int wr   = warp * 16;           // this warp's 16 query rows

    // staging: threads 0..319 handle Q+K of token tid; 320..639 handle V
    const bool qk_half = tid < 320;
    const int tok = qk_half ? tid : tid - 320;
    const int t   = tok >> 6;
    const int hs  = (tok >> 3) & 7;
    const int wsv = tok & 7;
    const int Hp = hw * 8 + hs;
    const int Wp = ww * 8 + wsv;
    const int h = (Hp + 4) & 63;
    const int w = (Wp + 4) & 63;
    const int rh = (Hp < 56) ? 0 : ((Hp < 60) ? 1 : 2);
    const int rw = (Wp < 56) ? 0 : ((Wp < 60) ? 1 : 2);
    if (qk_half)
        meta_s[tok] = (t * 15 + hs + wsv) | ((rh * 3 + rw) << 8);

    const int row = ((b * T_FRAMES + t) << 12) + (h << 6) + w;
    const float* qp = qkv + (size_t)row * (3 * DIM) + head * HDIM;

    const float LOG2E = 1.4426950408889634f;
    const float qs_f = 0.17677669529663687f * LOG2E;

    if (qk_half) {
        const float4* qv = (const float4*)qp;
        const float4* kv = (const float4*)(qp + DIM);
        #pragma unroll
        for (int m = 0; m < 8; ++m) {
            float4 f = qv[m];
            const int off = tok * ROWB + m * 8;
            *(u32*)(smc + OFF_QH + off)     = packh2(f.x * qs_f, f.y * qs_f);
            *(u32*)(smc + OFF_QH + off + 4) = packh2(f.z * qs_f, f.w * qs_f);
        }
        #pragma unroll
        for (int m = 0; m < 8; ++m) {
            float4 f = kv[m];
            const int off = tok * ROWB + m * 8;
            *(u32*)(smc + OFF_KH + off)     = packh2(f.x, f.y);
            *(u32*)(smc + OFF_KH + off + 4) = packh2(f.z, f.w);
        }
    } else {
        const float4* vv = (const float4*)(qp + 2 * DIM);
        #pragma unroll
        for (int m = 0; m < 8; ++m) {
            float4 f = vv[m];
            const int off = tok * ROWB + m * 8;
            *(u32*)(smc + OFF_VH + off)     = packh2(f.x, f.y);
            *(u32*)(smc + OFF_VH + off + 4) = packh2(f.z, f.w);
        }
    }
    // overlapped bias table: biasd[i] = (bias[i], bias[i+1]) (scaled by log2e)
    for (int idx = tid; idx < 1185; idx += 640) {
        float b0 = bias_table[idx * HEADS + head] * LOG2E;
        float b1 = (idx + 1 < 1185) ? bias_table[(idx + 1) * HEADS + head] * LOG2E : 0.f;
        *(float2*)(smc + OFF_BIASD + idx * 8) = make_float2(b0, b1);
    }

    __syncthreads();

    // per-thread row constants: biasd address offsets (ai-1)*8 and regions
    u32 aio[2]; int ri[2];
    #pragma unroll
    for (int hh = 0; hh < 2; ++hh) {
        int mv = meta_s[wr + g + 8 * hh];
        aio[hh] = (u32)(((mv & 255) + 111) * 8);   // (ai-1)*8, ai = bj+112
        ri[hh] = mv >> 8;
    }

    // ldmatrix per-lane address components
    const int l8  = lane & 7;
    const u32 krb = (u32)(l8 * ROWB + (lane >> 3) * 16);
    const u32 qrb = (u32)((wr + l8 + ((lane >> 3) & 1) * 8) * ROWB + (lane >> 4) * 16);
    const u32 vtb = smb + OFF_VH + (u32)(lane * ROWB);

    // Q A-fragments: [kt][4]
    u32 qa[2][4];
    #pragma unroll
    for (int kt = 0; kt < 2; ++kt)
        ldsm4(qa[kt][0], qa[kt][1], qa[kt][2], qa[kt][3],
              smb + OFF_QH + qrb + kt * 32);

    const u32 khb = smb + OFF_KH + krb;
    const u32 bd0 = smb + OFF_BIASD + aio[0];
    const u32 bd1 = smb + OFF_BIASD + aio[1];

    float oacc[4][4];
    #pragma unroll
    for (int n = 0; n < 4; ++n)
        #pragma unroll
        for (int e = 0; e < 4; ++e) oacc[n][e] = 0.f;
    float lsum[2] = {0.f, 0.f};

    float sacc[4][4];
    u32 ps[4][2];

    // ---- S block: sacc = masked_bias (paired LDS.64); sacc += Qh·Kh ----
    auto s_block = [&](int jb2) {
        #pragma unroll
        for (int n = 0; n < 4; ++n) {
            const int j0 = jb2 + 8 * n + 2 * t4;
            const int mj = meta_s[j0];          // j0+1: same region, bias idx -1
            const u32 bo = (u32)((mj & 255) * 8);
            const int rj = mj >> 8;
            const float2 d0 = lds64fv(bd0 - bo);   // (bias for j0+1, bias for j0)
            const float2 d1 = lds64fv(bd1 - bo);
            float* c = sacc[n];
            const bool m0 = (ri[0] == rj), m1 = (ri[1] == rj);
            c[0] = m0 ? d0.y : -1e4f;
            c[1] = m0 ? d0.x : -1e4f;
            c[2] = m1 ? d1.y : -1e4f;
            c[3] = m1 ? d1.x : -1e4f;
        }
        #pragma unroll
        for (int n = 0; n < 4; ++n) {
            u32 kh[4];
            ldsm4(kh[0], kh[1], kh[2], kh[3], khb + (jb2 + 8 * n) * ROWB);
            float* c = sacc[n];
            mma16816(c[0], c[1], c[2], c[3],
                     qa[0][0], qa[0][1], qa[0][2], qa[0][3], kh[0], kh[1]);
            mma16816(c[0], c[1], c[2], c[3],
                     qa[1][0], qa[1][1], qa[1][2], qa[1][3], kh[2], kh[3]);
        }
    };

    auto sm_n = [&](int n, u32& sum0, u32& sum1) {
        float* c = sacc[n];
        const u32 pk0 = h2exp2(packh2(c[0], c[1]));
        const u32 pk1 = h2exp2(packh2(c[2], c[3]));
        ps[n][0] = pk0;
        ps[n][1] = pk1;
        sum0 = hadd2(sum0, pk0);
        sum1 = hadd2(sum1, pk1);
    };

    auto pv_all = [&](int jb2) {
        const u32 vb = vtb + (u32)(jb2 * ROWB);
        #pragma unroll
        for (int n = 0; n < 4; ++n) {
            u32 vt[4];
            ldsm4t(vt[0], vt[1], vt[2], vt[3], vb + n * 16);
            float* c = oacc[n];
            mma16816(c[0], c[1], c[2], c[3],
                     ps[0][0], ps[0][1], ps[1][0], ps[1][1], vt[0], vt[1]);
            mma16816(c[0], c[1], c[2], c[3],
                     ps[2][0], ps[2][1], ps[3][0], ps[3][1], vt[2], vt[3]);
        }
    };

    auto flush_sums = [&](u32 sum0, u32 sum1) {
        float2 f0 = __half22float2(*(__half2*)&sum0);
        float2 f1 = __half22float2(*(__half2*)&sum1);
        lsum[0] += f0.x + f0.y;
        lsum[1] += f1.x + f1.y;
    };

    // ---- software-pipelined mainloop ----
    s_block(0);
    #pragma unroll 1
    for (int jc = 0; jc < 9; ++jc) {
        const int jb = jc * 32;
        u32 sum0 = 0, sum1 = 0;
        sm_n(0, sum0, sum1);
        sm_n(1, sum0, sum1);
        sm_n(2, sum0, sum1);
        sm_n(3, sum0, sum1);
        s_block(jb + 32);          // next S: tensor work covers softmax latency
        pv_all(jb);
        flush_sums(sum0, sum1);
    }
    {
        u32 sum0 = 0, sum1 = 0;
        sm_n(0, sum0, sum1);
        sm_n(1, sum0, sum1);
        sm_n(2, sum0, sum1);
        sm_n(3, sum0, sum1);
        pv_all(288);
        flush_sums(sum0, sum1);
    }

    #pragma unroll
    for (int hh = 0; hh < 2; ++hh) {
        float v = lsum[hh];
        v += __shfl_xor_sync(0xffffffffu, v, 1);
        v += __shfl_xor_sync(0xffffffffu, v, 2);
        lsum[hh] = 1.0f / v;
    }

    // fp16 scratch write
    #pragma unroll
    for (int hh = 0; hh < 2; ++hh) {
        const int r = wr + g + 8 * hh;
        u32* orow = g_scratch + (((size_t)(wb * NTOK + r)) * DIM + head * HDIM) / 2;
        const float inv = lsum[hh];
        #pragma unroll
        for (int n = 0; n < 4; ++n)
            orow[(8 * n + 2 * t4) >> 1] = packh2(oacc[n][2 * hh] * inv,
                                                 oacc[n][2 * hh + 1] * inv);
    }
}

// ---------------- projection kernel (fp16 hi-only, double-buffered smem) ----------------
// 512 threads / 16 warps as 4(m) x 4(n). out = Oh·Wh. Scratch already fp16.
#define PWROW 400                      // padded W/o row bytes (200 fp16)
#define OFF_PWH  0
#define OFF_POH0 76800
#define OFF_POH1 102400
#define PROJ_SMEM 128000

__global__ void __launch_bounds__(512)
proj_kernel(const float* __restrict__ pw, const float* __restrict__ pb,
            float* __restrict__ out, int nchunks)
{
    extern __shared__ char smc[];
    const u32 smb = (u32)__cvta_generic_to_shared(smc);
    const int tid = threadIdx.x, lane = tid & 31, warp = tid >> 5;
    const int g = lane >> 2, t4 = lane & 3;
    const int wm = warp >> 2, wn = warp & 3;   // 4 x 4
    const int m0 = wm * 16, n0 = wn * 48;

    // ---- stage W (fp16 hi only) once ----
    for (int idx = tid; idx < DIM * 96; idx += 512) {
        const int c = idx / 96, kp = idx % 96;
        float2 v = *(const float2*)(pw + c * DIM + kp * 2);
        *(u32*)(smc + OFF_PWH + c * PWROW + kp * 4) = packh2(v.x, v.y);
    }
    float pbv[6][2];
    #pragma unroll
    for (int nt = 0; nt < 6; ++nt) {
        float2 v = *(const float2*)(pb + n0 + nt * 8 + 2 * t4);
        pbv[nt][0] = v.x; pbv[nt][1] = v.y;
    }

    const int l8 = lane & 7;
    const u32 arb = (u32)((m0 + l8 + ((lane >> 3) & 1) * 8) * PWROW + (lane >> 4) * 16);
    const u32 brb = (u32)((l8 + (lane >> 4) * 8) * PWROW + ((lane >> 3) & 1) * 16);

    const u32 whb  = smb + OFF_PWH + brb;
    const u32 ohb0 = smb + OFF_POH0 + arb;
    const u32 ohb1 = smb + OFF_POH1 + arb;

    auto sts_chunk = [&](int bufsel, const u32* pre) {
        const u32 base = bufsel ? (u32)OFF_POH1 : (u32)OFF_POH0;
        #pragma unroll
        for (int it = 0; it < 12; ++it) {
            const int idx = tid + it * 512;
            const int tok = idx / 96, kp = idx % 96;
            *(u32*)(smc + base + tok * PWROW + kp * 4) = pre[it];
        }
    };
    auto ldg_chunk = [&](int c, u32* pre) {
        const u32* src = g_scratch + (size_t)c * (64 * 96);   // 96 u32 per token
        #pragma unroll
        for (int it = 0; it < 12; ++it)
            pre[it] = src[tid + it * 512];
    };

    const int stride = gridDim.x;
    u32 pre[12];
    int ci = blockIdx.x;
    if (ci < nchunks) {
        ldg_chunk(ci, pre);
        sts_chunk(0, pre);
        if (ci + stride < nchunks) ldg_chunk(ci + stride, pre);
    }
    __syncthreads();

    int bufsel = 0;
    #pragma unroll 1
    for (; ci < nchunks; ci += stride) {
        if (ci + stride < nchunks) {
            sts_chunk(bufsel ^ 1, pre);
            if (ci + 2 * stride < nchunks) ldg_chunk(ci + 2 * stride, pre);
        }

        float acc[6][4];
        #pragma unroll
        for (int nt = 0; nt < 6; ++nt)
            #pragma unroll
            for (int e = 0; e < 4; ++e) acc[nt][e] = 0.f;

        const u32 ohb = bufsel ? ohb1 : ohb0;
        #pragma unroll
        for (int ki = 0; ki < 12; ++ki) {
            u32 ah[4];
            ldsm4v(ah[0], ah[1], ah[2], ah[3], ohb + ki * 32);
            #pragma unroll
            for (int p = 0; p < 3; ++p) {
                u32 bh[4];
                const u32 bo = (u32)((n0 + 16 * p) * PWROW) + ki * 32;
                ldsm4(bh[0], bh[1], bh[2], bh[3], whb + bo);
                float* c0 = acc[2 * p];
                float* c1 = acc[2 * p + 1];
                mma16816(c0[0], c0[1], c0[2], c0[3], ah[0], ah[1], ah[2], ah[3], bh[0], bh[1]);
                mma16816(c1[0], c1[1], c1[2], c1[3], ah[0], ah[1], ah[2], ah[3], bh[2], bh[3]);
            }
        }
        __syncthreads();

        const int wbid = ci / 5, t = ci % 5;
        const int b = wbid >> 6, widx = wbid & 63;
        const int hw = widx >> 3, ww = widx & 7;
        #pragma unroll
        for (int hh = 0; hh < 2; ++hh) {
            const int s = m0 + g + 8 * hh;   // token 0..63
            const int hs = s >> 3, wsv = s & 7;
            const int h = (hw * 8 + hs + 4) & 63;
            const int w = (ww * 8 + wsv + 4) & 63;
            float* orow = out + ((size_t)((b * T_FRAMES + t) * 4096 + h * 64 + w)) * DIM;
            #pragma unroll
            for (int nt = 0; nt < 6; ++nt) {
                float2 v = make_float2(acc[nt][2 * hh]     + pbv[nt][0],
                                       acc[nt][2 * hh + 1] + pbv[nt][1]);
                *(float2*)(orow + n0 + nt * 8 + 2 * t4) = v;
            }
        }
        bufsel ^= 1;
    }
}

// ---------------- launch ----------------
extern "C" void kernel_launch(void* const* d_in, const int* in_sizes, int n_in,
                              void* d_out, int out_size)
{
    const float* qkv        = (const float*)d_in[0];
    const float* bias_table = (const float*)d_in[1];
    const float* pw         = (const float*)d_in[2];
    const float* pb         = (const float*)d_in[3];
    float* out = (float*)d_out;

    int B = in_sizes[0] / (T_FRAMES * 64 * 64 * 3 * DIM);
    if (B < 1) B = 1;
    if (B > 2) B = 2;   // scratch sized for B=2

    cudaFuncSetAttribute(attn_kernel, cudaFuncAttributeMaxDynamicSharedMemorySize, ATTN_SMEM);
    cudaFuncSetAttribute(proj_kernel, cudaFuncAttributeMaxDynamicSharedMemorySize, PROJ_SMEM);

    dim3 ag(B * 64, HEADS);
    attn_kernel<<<ag, 640, ATTN_SMEM>>>(qkv, bias_table);

    const int nchunks = B * 64 * T_FRAMES;
    int pgrid = nchunks < 148 ? nchunks : 148;
    proj_kernel<<<pgrid, 512, PROJ_SMEM>>>(pw, pb, out, nchunks);
}